// round 10
// baseline (speedup 1.0000x reference)
#include <cuda_runtime.h>
#include <cuda_bf16.h>
#include <cstdint>

// SoftPerspectiveShader: fused sample_textures + softmax_rgb_blend
// R9 = R8 with the compile fix (inline-PTX cvta.to.shared instead of the
// __cvta_generic_to_shared intrinsic, which broke the frontend in a lambda).
//
// Design: cp.async.cg double-buffered persistent pipeline. Seven measured
// rounds showed DRAM-busy pinned at ~28us with every idle-gap fix failing:
// warps burst 6 LDGs then sleep ~600cyc in phase. cp.async streams
// p2f/zbuf/dists into SMEM so the copy path keeps traffic in flight
// continuously; each thread stages ONLY its own pixel's data -> no
// __syncthreads, per-thread wait_group ordering. Persistent 1-wave grid
// (4 blocks/SM, SMEM-limited) removes the 5.5-wave tail. Compute = R1
// branch structure + R5 slim math (rel_err 4.3e-7). Softmax is effectively
// one-hot (GAMMA=1e-4, zbuf sorted): w==0 fragments contribute exactly 0,
// so their bary/fcol gathers are skipped.

#define SIGMA_INV 1e4f
#define GAMMA_INV 1e4f
#define ZFAR_F    100.0f
#define ZRANGE_F  99.0f
#define EPS_F     1e-10f

#define THREADS  256
#define NBLOCKS  608   // 4 blocks/SM x 152 SMs (GB300)

__device__ __forceinline__ uint32_t smem_u32(const void* p) {
    uint32_t a;
    asm("{ .reg .u64 t; cvta.to.shared.u64 t, %1; cvt.u32.u64 %0, t; }"
        : "=r"(a) : "l"(p));
    return a;
}

__device__ __forceinline__ void cpa16(uint32_t dst, const void* src) {
    asm volatile("cp.async.cg.shared.global [%0], [%1], 16;"
                 :: "r"(dst), "l"(src));
}

__global__ __launch_bounds__(THREADS) void soft_shader_pipe(
    const float4* __restrict__ p2f4,   // pix_to_face bits as float4 [P*2]
    const float*  __restrict__ bary,   // [P][8][3]
    const float4* __restrict__ zbuf,   // [P*2]
    const float4* __restrict__ dists,  // [P*2]
    const float*  __restrict__ fcol,   // [F][3][3]
    float4*       __restrict__ out,    // [P]
    int nchunks)                       // P / THREADS
{
    // 2 buffers x 6 vectors x 256 threads x 16B = 48KB
    __shared__ float4 sbuf[2][6][THREADS];

    const int t      = threadIdx.x;
    const int stride = gridDim.x;
    int chunk = blockIdx.x;
    if (chunk >= nchunks) return;

    // stage chunk c's per-thread data into buffer b (6 x cp.async.cg 16B)
    auto stage = [&](int c, int b) {
        size_t px = (size_t)c * THREADS + t;
        cpa16(smem_u32(&sbuf[b][0][t]), p2f4  + 2 * px);
        cpa16(smem_u32(&sbuf[b][1][t]), p2f4  + 2 * px + 1);
        cpa16(smem_u32(&sbuf[b][2][t]), zbuf  + 2 * px);
        cpa16(smem_u32(&sbuf[b][3][t]), zbuf  + 2 * px + 1);
        cpa16(smem_u32(&sbuf[b][4][t]), dists + 2 * px);
        cpa16(smem_u32(&sbuf[b][5][t]), dists + 2 * px + 1);
    };

    stage(chunk, 0);
    asm volatile("cp.async.commit_group;");
    int buf = 0;

    while (chunk < nchunks) {
        int next = chunk + stride;
        if (next < nchunks) stage(next, buf ^ 1);
        asm volatile("cp.async.commit_group;");   // (possibly empty) group
        asm volatile("cp.async.wait_group 1;");   // current buffer complete

        const float4 vf0 = sbuf[buf][0][t], vf1 = sbuf[buf][1][t];
        const float4 vz0 = sbuf[buf][2][t], vz1 = sbuf[buf][3][t];
        const float4 vd0 = sbuf[buf][4][t], vd1 = sbuf[buf][5][t];

        int faces[8] = { __float_as_int(vf0.x), __float_as_int(vf0.y),
                         __float_as_int(vf0.z), __float_as_int(vf0.w),
                         __float_as_int(vf1.x), __float_as_int(vf1.y),
                         __float_as_int(vf1.z), __float_as_int(vf1.w) };
        float zv[8] = { vz0.x, vz0.y, vz0.z, vz0.w, vz1.x, vz1.y, vz1.z, vz1.w };
        float dv[8] = { vd0.x, vd0.y, vd0.z, vd0.w, vd1.x, vd1.y, vd1.z, vd1.w };

        const size_t p = (size_t)chunk * THREADS + t;

        // pass 1: alpha product + z_inv_max
        float zinv[8];
        float zmax = EPS_F;
        float keep = 1.0f;
#pragma unroll
        for (int k = 0; k < 8; k++) {
            bool  m  = faces[k] >= 0;
            float e  = __expf(dv[k] * SIGMA_INV);               // exp(d/sigma)
            float pr = m ? __fdividef(1.0f, 1.0f + e) : 0.0f;   // sigmoid(-d/sigma)
            keep *= (1.0f - pr);
            float zi = m ? ((ZFAR_F - zv[k]) / ZRANGE_F) : 0.0f; // true div (matches ref)
            zinv[k] = zi;
            zmax = fmaxf(zmax, zi);
        }

        float delta = fmaxf(__expf((EPS_F - zmax) * GAMMA_INV), EPS_F);
        float denom = delta;
        float r = 0.0f, g = 0.0f, b = 0.0f;

        // pass 2: weights + sparse gathers (one-hot softmax skip)
#pragma unroll
        for (int k = 0; k < 8; k++) {
            bool  m  = faces[k] >= 0;
            float e  = __expf(dv[k] * SIGMA_INV);
            float pr = m ? __fdividef(1.0f, 1.0f + e) : 0.0f;
            float w  = pr * __expf((zinv[k] - zmax) * GAMMA_INV); // exp(0)=1 at argmax
            denom += w;
            if (w > 0.0f) {
                const float* bc = bary + p * 24 + (size_t)k * 3;
                float b0 = bc[0], b1 = bc[1], b2 = bc[2];
                const float* fc = fcol + (size_t)faces[k] * 9;
                float t0 = b0 * fc[0] + b1 * fc[3] + b2 * fc[6];
                float t1 = b0 * fc[1] + b1 * fc[4] + b2 * fc[7];
                float t2 = b0 * fc[2] + b1 * fc[5] + b2 * fc[8];
                r += w * t0; g += w * t1; b += w * t2;
            }
        }

        float inv = __fdividef(1.0f, denom);
        float4 o;
        o.x = (r + delta) * inv;   // background = (1,1,1)
        o.y = (g + delta) * inv;
        o.z = (b + delta) * inv;
        o.w = keep;                // 1 - alpha
        out[p] = o;

        buf ^= 1;
        chunk = next;
    }
}

extern "C" void kernel_launch(void* const* d_in, const int* in_sizes, int n_in,
                              void* d_out, int out_size) {
    const float4* p2f4  = (const float4*)d_in[0];
    const float*  bary  = (const float*)d_in[1];
    const float4* zbufp = (const float4*)d_in[2];
    const float4* dist  = (const float4*)d_in[3];
    const float*  fcol  = (const float*)d_in[4];
    int P = in_sizes[0] / 8;          // N*H*W pixels (1,048,576)
    int nchunks = P / THREADS;        // 4096 (P divisible by 256)

    soft_shader_pipe<<<NBLOCKS, THREADS>>>(
        p2f4, bary, zbufp, dist, fcol, (float4*)d_out, nchunks);
}

// round 11
// speedup vs baseline: 1.2851x; 1.2851x over previous
#include <cuda_runtime.h>
#include <cuda_bf16.h>

// SoftPerspectiveShader: fused sample_textures + softmax_rgb_blend
// R10 = EXACT R1 (best: 42.5us kernel, DRAM 66%) + one surgical change:
// bary[p][0] sits at p*96, 16B-aligned, addressed by p alone (independent
// of p2f), and fragment k=0 is the softmax winner with prob 1-1/200001.
// So a 7th front-batched LDG.128 speculatively loads it; the unrolled
// blend loop uses those registers for k==0 and falls back to the scalar
// gather for k>=1. No select chains, no p2f-dependent prefetch (the R2/R4
// failure mode), +4 regs capped at 51 (__launch_bounds__(256,5)) to keep
// 5 blocks/SM like R1. All arithmetic is bit-identical to R1.

#define SIGMA_F 1e-4f
#define GAMMA_F 1e-4f
#define ZNEAR_F 1.0f
#define ZFAR_F  100.0f
#define EPS_F   1e-10f

__global__ __launch_bounds__(256, 5) void soft_shader_kernel(
    const int4*   __restrict__ p2f,    // [P][2] int4  (K=8)
    const float*  __restrict__ bary,   // [P][8][3]
    const float4* __restrict__ zbuf,   // [P][2] float4
    const float4* __restrict__ dists,  // [P][2] float4
    const float*  __restrict__ fcol,   // [F][3][3]
    float4*       __restrict__ out,    // [P]
    int P)
{
    int p = blockIdx.x * blockDim.x + threadIdx.x;
    if (p >= P) return;

    // ---- front batch: 7 independent LDG.128 (MLP_p1 = 7) ----
    const int4   fa = p2f[2 * p],   fb = p2f[2 * p + 1];
    const float4 za = zbuf[2 * p],  zb = zbuf[2 * p + 1];
    const float4 da = dists[2 * p], db = dists[2 * p + 1];
    const float4 b4 = *(const float4*)(bary + (size_t)p * 24);  // bary[p][0][0..2] (+1 extra)

    int   faces[8] = {fa.x, fa.y, fa.z, fa.w, fb.x, fb.y, fb.z, fb.w};
    float zv[8]    = {za.x, za.y, za.z, za.w, zb.x, zb.y, zb.z, zb.w};
    float dv[8]    = {da.x, da.y, da.z, da.w, db.x, db.y, db.z, db.w};

    float prob[8], zinv[8];
    float zmax = EPS_F;      // z_inv_max = max(max_k z_inv, EPS)
    float keep = 1.0f;       // prod(1 - prob) = 1 - alpha

#pragma unroll
    for (int k = 0; k < 8; k++) {
        bool  m  = faces[k] >= 0;
        // sigmoid(-d/sigma) = 1/(1+exp(d/sigma))
        float pr = m ? (1.0f / (1.0f + expf(dv[k] / SIGMA_F))) : 0.0f;
        prob[k] = pr;
        keep *= (1.0f - pr);
        float zi = m ? ((ZFAR_F - zv[k]) / (ZFAR_F - ZNEAR_F)) : 0.0f;
        zinv[k] = zi;
        zmax = fmaxf(zmax, zi);
    }

    float delta = fmaxf(expf((EPS_F - zmax) / GAMMA_F), EPS_F);
    float denom = delta;
    float r = 0.0f, g = 0.0f, b = 0.0f;

#pragma unroll
    for (int k = 0; k < 8; k++) {
        float w = prob[k] * expf((zinv[k] - zmax) / GAMMA_F);
        denom += w;
        if (w > 0.0f) {
            // w > 0 implies faces[k] >= 0
            float b0, b1, b2;
            if (k == 0) {            // compile-time: prefetched aligned vector
                b0 = b4.x; b1 = b4.y; b2 = b4.z;
            } else {
                const float* bc = bary + (size_t)p * 24 + (size_t)k * 3;
                b0 = bc[0]; b1 = bc[1]; b2 = bc[2];
            }
            const float* fc = fcol + (size_t)faces[k] * 9;
            float t0 = b0 * fc[0] + b1 * fc[3] + b2 * fc[6];
            float t1 = b0 * fc[1] + b1 * fc[4] + b2 * fc[7];
            float t2 = b0 * fc[2] + b1 * fc[5] + b2 * fc[8];
            r += w * t0;
            g += w * t1;
            b += w * t2;
        }
    }

    float inv = 1.0f / denom;
    float4 o;
    o.x = (r + delta) * inv;   // background = (1,1,1): + delta*1/denom
    o.y = (g + delta) * inv;
    o.z = (b + delta) * inv;
    o.w = keep;                // 1 - alpha
    out[p] = o;
}

extern "C" void kernel_launch(void* const* d_in, const int* in_sizes, int n_in,
                              void* d_out, int out_size) {
    const int*   p2f   = (const int*)d_in[0];
    const float* bary  = (const float*)d_in[1];
    const float* zbufp = (const float*)d_in[2];
    const float* dist  = (const float*)d_in[3];
    const float* fcol  = (const float*)d_in[4];
    int P = in_sizes[0] / 8;   // N*H*W pixels

    int threads = 256;
    int blocks  = (P + threads - 1) / threads;
    soft_shader_kernel<<<blocks, threads>>>(
        (const int4*)p2f, bary, (const float4*)zbufp, (const float4*)dist,
        fcol, (float4*)d_out, P);
}